// round 15
// baseline (speedup 1.0000x reference)
#include <cuda_runtime.h>
#include <math.h>

#define NN 8192
#define WD 64
#define OUTD 256
#define IFACED 471
#define CD 727
#define FCD 2908
#define J4 727
#define LKS 64
#define KS2 32

typedef unsigned long long ull;

__device__ __align__(16) float g_seq[5 * WD];
__device__ float g_h[CD], g_c[CD];
__device__ __align__(16) float g_zb[5 * FCD];
__device__ float g_oppart[KS2 * CD];
__device__ float g_outv[OUTD];
__device__ float g_kwn[WD];
__device__ float g_krn[4 * WD];
__device__ float g_bread[4], g_bwrite;
__device__ __align__(16) float g_erase[WD];
__device__ __align__(16) float g_writev[WD];
__device__ float g_free[4], g_ag, g_wg;
__device__ float g_rm[12];
__device__ float g_usage[NN];
__device__ int   g_rank_[NN];
__device__ float g_Walloc[NN];
__device__ float g_ew[NN];
__device__ float g_sumw;
__device__ __align__(16) float g_Ww[NN];
__device__ __align__(16) float g_M[NN * WD];
__device__ __align__(16) float g_Wfwd[NN * 4];
__device__ __align__(16) float g_Wbwd[NN * 4];
__device__ float g_S1[256], g_S2[256], g_sumr[4];
__device__ int g_rcnt;

__device__ __forceinline__ float sigm(float x) { return 1.f / (1.f + expf(-x)); }
__device__ __forceinline__ float sp(float x) { return x > 20.f ? x : log1pf(expf(x)); }

// ---- packed f32x2 helpers (sm_103a) ----
__device__ __forceinline__ ull pk2(float lo, float hi) {
    ull d; asm("mov.b64 %0, {%1,%2};" : "=l"(d) : "f"(lo), "f"(hi)); return d;
}
__device__ __forceinline__ float2 up2(ull v) {
    float2 r; asm("mov.b64 {%0,%1}, %2;" : "=f"(r.x), "=f"(r.y) : "l"(v)); return r;
}
__device__ __forceinline__ ull fma2_(ull a, ull b, ull c) {
    ull d; asm("fma.rn.f32x2 %0, %1, %2, %3;" : "=l"(d) : "l"(a), "l"(b), "l"(c)); return d;
}
__device__ __forceinline__ ull add2_(ull a, ull b) {
    ull d; asm("add.rn.f32x2 %0, %1, %2;" : "=l"(d) : "l"(a), "l"(b)); return d;
}
__device__ __forceinline__ ull mul2_(ull a, ull b) {
    ull d; asm("mul.rn.f32x2 %0, %1, %2;" : "=l"(d) : "l"(a), "l"(b)); return d;
}

// init: block 0 does seq/h/c; all 8 blocks zero the 5 z accumulators
__global__ void k_init(const float* __restrict__ x, const float* __restrict__ dk,
                       const float* __restrict__ db, const float* __restrict__ h,
                       const float* __restrict__ c, const float* __restrict__ read_v) {
    const int t = threadIdx.x, b = blockIdx.x;
    for (int i = b * 1024 + t; i < 5 * FCD; i += 8 * 1024) g_zb[i] = 0.f;
    if (b) return;
    if (t < WD) {
        float acc = db[t];
#pragma unroll 8
        for (int k = 0; k < 256; k++) acc += x[k] * dk[k * WD + t];
        g_seq[t] = acc;
    }
    if (t < 256) g_seq[WD + t] = read_v[t];
    if (t < CD) { g_h[t] = h[t]; g_c[t] = c[t]; }
}

// split-K LSTM matvec (R5 numerics), per-step z-buffer
__global__ void __launch_bounds__(128) k_lstmA(const float* __restrict__ lstm_k,
                                               const float* __restrict__ lstm_r, int t) {
    __shared__ float s_h[12];
    const int j4 = blockIdx.x * 128 + threadIdx.x;
    const int j4c = min(j4, J4 - 1);
    const int kc = blockIdx.y;
    const int k0 = kc * 12;
    const int kn = min(12, CD - k0);
    const float4* lr = (const float4*)lstm_r;
    float4 rv[12];
#pragma unroll
    for (int k = 0; k < 12; k++) {
        int row = min(k0 + k, CD - 1);
        rv[k] = lr[(size_t)row * J4 + j4c];
    }
    float4 kv = ((const float4*)lstm_k)[kc * J4 + j4c];
    if (threadIdx.x < 12) s_h[threadIdx.x] = (threadIdx.x < kn) ? g_h[k0 + threadIdx.x] : 0.f;
    __syncthreads();
    if (j4 >= J4) return;
    float xs = g_seq[t * WD + kc];
    float ax = xs * kv.x, ay = xs * kv.y, az = xs * kv.z, aw = xs * kv.w;
#pragma unroll
    for (int k = 0; k < 12; k++) {
        float hv = s_h[k];
        ax += hv * rv[k].x; ay += hv * rv[k].y; az += hv * rv[k].z; aw += hv * rv[k].w;
    }
    float* zb = g_zb + t * FCD;
    atomicAdd(&zb[j4 * 4 + 0], ax);
    atomicAdd(&zb[j4 * 4 + 1], ay);
    atomicAdd(&zb[j4 * 4 + 2], az);
    atomicAdd(&zb[j4 * 4 + 3], aw);
}

// gate: z(t)+bias -> h,c   (no re-zero needed: per-step buffers)
__global__ void k_gate(const float* __restrict__ lstm_b, int t) {
    const int j = threadIdx.x;
    if (j >= CD) return;
    const float* zb = g_zb + t * FCD;
    float zi = zb[j] + lstm_b[j];
    float zf = zb[CD + j] + lstm_b[CD + j];
    float zg = zb[2 * CD + j] + lstm_b[2 * CD + j];
    float zo = zb[3 * CD + j] + lstm_b[3 * CD + j];
    float cn = sigm(zf) * g_c[j] + sigm(zi) * tanhf(zg);
    g_c[j] = cn;
    g_h[j] = sigm(zo) * tanhf(cn);
}

__global__ void k_proj(const float* __restrict__ Wout, const float* __restrict__ Wif) {
    __shared__ float sh[23];
    const int j = blockIdx.x * 256 + threadIdx.x;
    const int kc = blockIdx.y;
    const int k0 = kc * 23;
    const int kn = min(23, CD - k0);
    if (threadIdx.x < 23) sh[threadIdx.x] = (threadIdx.x < kn) ? g_h[k0 + threadIdx.x] : 0.f;
    __syncthreads();
    if (j >= CD) return;
    float acc = 0.f;
    if (j < 256) {
#pragma unroll
        for (int k = 0; k < 23; k++) {
            if (k >= kn) break;
            acc += sh[k] * Wout[(size_t)(k0 + k) * 256 + j];
        }
    } else {
        int jj = j - 256;
#pragma unroll
        for (int k = 0; k < 23; k++) {
            if (k >= kn) break;
            acc += sh[k] * Wif[(size_t)(k0 + k) * IFACED + jj];
        }
    }
    g_oppart[kc * CD + j] = acc;
}

__global__ void k_parse() {
    __shared__ float sif[IFACED];
    const int t = threadIdx.x;
    if (t < CD) {
        float v = 0.f;
#pragma unroll
        for (int p = 0; p < KS2; p++) v += g_oppart[p * CD + t];
        if (t < 256) g_outv[t] = v; else sif[t - 256] = v;
    }
    __syncthreads();
    const int w = t >> 5, lane = t & 31;
    if (w == 0) {
        float s = 0.f;
        for (int e = lane; e < 64; e += 32) { float v = sif[260 + e]; s += v * v; }
        for (int o = 16; o; o >>= 1) s += __shfl_xor_sync(0xffffffffu, s, o);
        float inv = rsqrtf(fmaxf(s, 1e-12f));
        for (int e = lane; e < 64; e += 32) g_kwn[e] = sif[260 + e] * inv;
    } else if (w <= 4) {
        int r = w - 1;
        float s = 0.f;
        for (int e = lane; e < 64; e += 32) { float v = sif[r * 64 + e]; s += v * v; }
        for (int o = 16; o; o >>= 1) s += __shfl_xor_sync(0xffffffffu, s, o);
        float inv = rsqrtf(fmaxf(s, 1e-12f));
        for (int e = lane; e < 64; e += 32) g_krn[r * 64 + e] = sif[r * 64 + e] * inv;
    } else if (w == 5) {
        if (lane < 4) g_bread[lane] = 1.f + sp(sif[256 + lane]);
        if (lane == 4) g_bwrite = 1.f + sp(sif[324]);
        if (lane >= 8 && lane < 12) g_free[lane - 8] = sigm(sif[453 + lane - 8]);
        if (lane == 12) g_ag = sigm(sif[457]);
        if (lane == 13) g_wg = sigm(sif[458]);
        if (lane >= 16 && lane < 20) {
            int r = lane - 16;
            float e0 = expf(sif[459 + r]);
            float e1 = expf(sif[463 + r]);
            float e2 = expf(sif[467 + r]);
            float si = 1.f / (e0 + e1 + e2);
            g_rm[r] = e0 * si; g_rm[4 + r] = e1 * si; g_rm[8 + r] = e2 * si;
        }
    } else if (w == 6) {
        for (int e = lane; e < 64; e += 32) {
            g_erase[e] = sigm(sif[325 + e]);
            g_writev[e] = sif[389 + e];
        }
    }
}

__device__ __forceinline__ float usage_mk(float u, float4 wr, float ww,
                                          float f0, float f1, float f2, float f3) {
    float ret = 1.f;
    ret *= (1.f - f0 * wr.x);
    ret *= (1.f - f1 * wr.y);
    ret *= (1.f - f2 * wr.z);
    ret *= (1.f - f3 * wr.w);
    return (u + ww - u * ww) * ret;
}

// blocks 0..255: usage (deterministic recompute) + brute-force stable rank + zeroing
// blocks 256..319: write content scores
__global__ void k_rankws(const float* __restrict__ usage_in, const float* __restrict__ Wread_in,
                         const float* __restrict__ Wwrite_in, const float* __restrict__ M) {
    __shared__ ull s_k[256];
    __shared__ float bsum[8];
    const int b = blockIdx.x, tid = threadIdx.x;
    if (b < 256) {
        const int bi = b >> 5, bj = b & 31;
        const float4* wr4 = (const float4*)Wread_in;
        const float f0 = g_free[0], f1 = g_free[1], f2 = g_free[2], f3 = g_free[3];
        {
            const int jg = bj * 256 + tid;
            float uu = usage_mk(usage_in[jg], wr4[jg], Wwrite_in[jg], f0, f1, f2, f3);
            s_k[tid] = ((ull)__float_as_uint(uu) << 13) | (unsigned)jg;
        }
        __syncthreads();
        const int i0 = bi * 1024 + tid * 4;
        ull ki[4];
#pragma unroll
        for (int m = 0; m < 4; m++) {
            int i = i0 + m;
            float uu = usage_mk(usage_in[i], wr4[i], Wwrite_in[i], f0, f1, f2, f3);
            ki[m] = ((ull)__float_as_uint(uu) << 13) | (unsigned)i;
            if (bj == 0) g_usage[i] = uu;
        }
        int c0 = 0, c1 = 0, c2 = 0, c3 = 0;
#pragma unroll 8
        for (int jj = 0; jj < 256; jj++) {
            ull kj = s_k[jj];
            c0 += (kj < ki[0]); c1 += (kj < ki[1]); c2 += (kj < ki[2]); c3 += (kj < ki[3]);
        }
        atomicAdd(&g_rank_[i0 + 0], c0);
        atomicAdd(&g_rank_[i0 + 1], c1);
        atomicAdd(&g_rank_[i0 + 2], c2);
        atomicAdd(&g_rank_[i0 + 3], c3);
        if (bi == 0) {
            float4 z4 = make_float4(0.f, 0.f, 0.f, 0.f);
            ((float4*)g_Wfwd)[bj * 256 + tid] = z4;
            ((float4*)g_Wbwd)[bj * 256 + tid] = z4;
            if (bj == 0) {
                g_S1[tid] = 0.f; g_S2[tid] = 0.f;
                if (tid < 4) g_sumr[tid] = 0.f;
                if (tid == 0) g_sumw = 0.f;
            }
        }
    } else {
        const int w = tid >> 5, lane = tid & 31;
        const int wg = (b - 256) * 8 + w;
        const float ka = g_kwn[lane], kb = g_kwn[lane + 32];
        const float bw = g_bwrite;
        float local = 0.f;
        for (int rr = 0; rr < 16; rr++) {
            int i = wg * 16 + rr;
            const float* row = M + (size_t)i * WD;
            float a0 = row[lane], a1 = row[lane + 32];
            float ss = a0 * a0 + a1 * a1;
            float d = a0 * ka + a1 * kb;
            for (int o = 16; o; o >>= 1) {
                ss += __shfl_xor_sync(0xffffffffu, ss, o);
                d += __shfl_xor_sync(0xffffffffu, d, o);
            }
            if (lane == 0) {
                float e = expf(bw * d * rsqrtf(fmaxf(ss, 1e-12f)));
                g_ew[i] = e;
                local += e;
            }
        }
        if (lane == 0) bsum[w] = local;
        __syncthreads();
        if (tid == 0) {
            float s = 0.f;
            for (int k = 0; k < 8; k++) s += bsum[k];
            atomicAdd(&g_sumw, s);
        }
    }
}

// alloc: scatter by rank -> exclusive cumprod -> W_alloc; also computes g_Ww
__global__ void k_alloc() {
    __shared__ float s_s[NN];
    __shared__ float wtot[32];
    const int t = threadIdx.x;
    for (int i = t; i < NN; i += 1024) s_s[g_rank_[i]] = g_usage[i];
    __syncthreads();
    float loc[8], p = 1.f;
#pragma unroll
    for (int m = 0; m < 8; m++) { loc[m] = p; p *= s_s[t * 8 + m]; }
    const int lane = t & 31, w = t >> 5;
    float sc = p;
    for (int o = 1; o < 32; o <<= 1) {
        float v = __shfl_up_sync(0xffffffffu, sc, o);
        if (lane >= o) sc *= v;
    }
    if (lane == 31) wtot[w] = sc;
    __syncthreads();
    if (w == 0) {
        float s2 = wtot[lane];
        for (int o = 1; o < 32; o <<= 1) {
            float z = __shfl_up_sync(0xffffffffu, s2, o);
            if (lane >= o) s2 *= z;
        }
        wtot[lane] = s2;
    }
    __syncthreads();
    float excl = __shfl_up_sync(0xffffffffu, sc, 1);
    if (lane == 0) excl = 1.f;
    float pref = (w > 0 ? wtot[w - 1] : 1.f) * excl;
#pragma unroll
    for (int m = 0; m < 8; m++) s_s[t * 8 + m] = pref * loc[m];
    __syncthreads();
    const float inv_s = 1.f / g_sumw;
    const float wgt = g_wg, ag = g_ag, iag = 1.f - g_ag;
    for (int i = t; i < NN; i += 1024) {
        float u = g_usage[i];
        float wa = (1.f - u) * s_s[g_rank_[i]];
        g_Walloc[i] = wa;
        g_Ww[i] = wgt * (ag * wa + iag * g_ew[i] * inv_s);
        g_rank_[i] = 0;
    }
}

__global__ void k_writeM(const float* __restrict__ M) {
    const int e4 = blockIdx.x * 256 + threadIdx.x;
    const int i = e4 >> 4, wc = (e4 & 15) << 2;
    const float ww = g_Ww[i];
    float4 m = ((const float4*)M)[e4];
    float4 er = *(const float4*)(g_erase + wc);
    float4 wv = *(const float4*)(g_writev + wc);
    float4 o;
    o.x = m.x * (1.f - ww * er.x) + ww * wv.x;
    o.y = m.y * (1.f - ww * er.y) + ww * wv.y;
    o.z = m.z * (1.f - ww * er.z) + ww * wv.z;
    o.w = m.w * (1.f - ww * er.w) + ww * wv.w;
    ((float4*)g_M)[e4] = o;
}

// fused: W_fwd = L_new @ Wr, W_bwd = L_new^T @ Wr; L_new on the fly; f32x2 packed;
// diagonal via epilogue subtraction
__global__ void __launch_bounds__(256) k_link(const float* __restrict__ L,
                                              const float* __restrict__ Wprec,
                                              const float* __restrict__ Wread) {
    __shared__ float s_ww[512];
    __shared__ float s_wr[512 * 4];
    __shared__ float s_red[8][1024];
    const int jb = blockIdx.x, ib = blockIdx.y;
    const int i0 = ib * 512;
    for (int k = threadIdx.x; k < 512; k += 256) {
        s_ww[k] = g_Ww[i0 + k];
        float4 v = ((const float4*)Wread)[i0 + k];
        s_wr[k * 4] = v.x; s_wr[k * 4 + 1] = v.y; s_wr[k * 4 + 2] = v.z; s_wr[k * 4 + 3] = v.w;
    }
    __syncthreads();
    const int w = threadIdx.x >> 5, lane = threadIdx.x & 31;
    const int j0 = jb * 256 + lane * 4;

    ull tj2[4], wpj2[4], wrj2[4][4], bwd2[4][4];
#pragma unroll
    for (int cc = 0; cc < 2; cc++)
#pragma unroll
        for (int p = 0; p < 2; p++) {
            int q = cc * 2 + p;
            int jj = j0 + cc * 128 + p * 2;
            tj2[q] = pk2(1.f - g_Ww[jj], 1.f - g_Ww[jj + 1]);
            wpj2[q] = pk2(Wprec[jj], Wprec[jj + 1]);
#pragma unroll
            for (int r = 0; r < 4; r++) {
                wrj2[q][r] = pk2(Wread[jj * 4 + r], Wread[(jj + 1) * 4 + r]);
                bwd2[q][r] = 0ull;
            }
        }
    const int c4 = j0 >> 2;
    float4 a0, a1, b0, b1;
    {
        const float4* LrA = (const float4*)(L + (size_t)(i0 + w) * NN);
        const float4* LrB = (const float4*)(L + (size_t)(i0 + w + 8) * NN);
        a0 = __ldcs(LrA + c4); a1 = __ldcs(LrA + c4 + 32);
        b0 = __ldcs(LrB + c4); b1 = __ldcs(LrB + c4 + 32);
    }
    for (int it = 0; it < 32; it++) {
        const int il = w + it * 16;
        const int ia = i0 + il, ib2 = ia + 8;
        float4 ca0 = a0, ca1 = a1, cb0 = b0, cb1 = b1;
        if (it < 31) {
            const int iln = il + 16;
            const float4* LrA = (const float4*)(L + (size_t)(i0 + iln) * NN);
            const float4* LrB = (const float4*)(L + (size_t)(i0 + iln + 8) * NN);
            a0 = __ldcs(LrA + c4); a1 = __ldcs(LrA + c4 + 32);
            b0 = __ldcs(LrB + c4); b1 = __ldcs(LrB + c4 + 32);
        }
        float fa[4], fb[4];
        {
            float ww = s_ww[il];
            ull ww2 = pk2(ww, ww), wwn2 = pk2(-ww, -ww);
            ull le[4] = {pk2(ca0.x, ca0.y), pk2(ca0.z, ca0.w), pk2(ca1.x, ca1.y), pk2(ca1.z, ca1.w)};
            ull f2[4] = {0ull, 0ull, 0ull, 0ull};
            ull wri2[4];
#pragma unroll
            for (int r = 0; r < 4; r++) { float s = s_wr[il * 4 + r]; wri2[r] = pk2(s, s); }
#pragma unroll
            for (int q = 0; q < 4; q++) {
                ull nl2 = fma2_(add2_(tj2[q], wwn2), le[q], mul2_(ww2, wpj2[q]));
#pragma unroll
                for (int r = 0; r < 4; r++) {
                    f2[r] = fma2_(nl2, wrj2[q][r], f2[r]);
                    bwd2[q][r] = fma2_(nl2, wri2[r], bwd2[q][r]);
                }
            }
#pragma unroll
            for (int r = 0; r < 4; r++) { float2 t = up2(f2[r]); fa[r] = t.x + t.y; }
        }
        {
            float ww = s_ww[il + 8];
            ull ww2 = pk2(ww, ww), wwn2 = pk2(-ww, -ww);
            ull le[4] = {pk2(cb0.x, cb0.y), pk2(cb0.z, cb0.w), pk2(cb1.x, cb1.y), pk2(cb1.z, cb1.w)};
            ull f2[4] = {0ull, 0ull, 0ull, 0ull};
            ull wri2[4];
#pragma unroll
            for (int r = 0; r < 4; r++) { float s = s_wr[(il + 8) * 4 + r]; wri2[r] = pk2(s, s); }
#pragma unroll
            for (int q = 0; q < 4; q++) {
                ull nl2 = fma2_(add2_(tj2[q], wwn2), le[q], mul2_(ww2, wpj2[q]));
#pragma unroll
                for (int r = 0; r < 4; r++) {
                    f2[r] = fma2_(nl2, wrj2[q][r], f2[r]);
                    bwd2[q][r] = fma2_(nl2, wri2[r], bwd2[q][r]);
                }
            }
#pragma unroll
            for (int r = 0; r < 4; r++) { float2 t = up2(f2[r]); fb[r] = t.x + t.y; }
        }
#pragma unroll
        for (int o = 16; o; o >>= 1) {
#pragma unroll
            for (int r = 0; r < 4; r++) {
                fa[r] += __shfl_xor_sync(0xffffffffu, fa[r], o);
                fb[r] += __shfl_xor_sync(0xffffffffu, fb[r], o);
            }
        }
        if (lane < 4) {
            float fv = lane == 0 ? fa[0] : lane == 1 ? fa[1] : lane == 2 ? fa[2] : fa[3];
            atomicAdd(&g_Wfwd[ia * 4 + lane], fv);
            float gv = lane == 0 ? fb[0] : lane == 1 ? fb[1] : lane == 2 ? fb[2] : fb[3];
            atomicAdd(&g_Wfwd[ib2 * 4 + lane], gv);
        }
    }
#pragma unroll
    for (int cc = 0; cc < 2; cc++)
#pragma unroll
        for (int p = 0; p < 2; p++) {
            int q = cc * 2 + p;
            int col = cc * 128 + lane * 4 + p * 2;
#pragma unroll
            for (int r = 0; r < 4; r++) {
                float2 t = up2(bwd2[q][r]);
                s_red[w][col * 4 + r] = t.x;
                s_red[w][(col + 1) * 4 + r] = t.y;
            }
        }
    __syncthreads();
#pragma unroll
    for (int qq = 0; qq < 4; qq++) {
        int pos = qq * 256 + threadIdx.x;
        float v = 0.f;
#pragma unroll
        for (int ww2 = 0; ww2 < 8; ww2++) v += s_red[ww2][pos];
        atomicAdd(&g_Wbwd[jb * 1024 + pos], v);
    }
    if (ib == (jb >> 1)) {
        const int i = jb * 256 + threadIdx.x;
        const int il = i - i0;
        float wwi = s_ww[il];
        float nl = (1.f - 2.f * wwi) * __ldg(L + (size_t)i * NN + i) + wwi * __ldg(Wprec + i);
#pragma unroll
        for (int r = 0; r < 4; r++) {
            float v = nl * s_wr[il * 4 + r];
            atomicAdd(&g_Wfwd[i * 4 + r], -v);
            atomicAdd(&g_Wbwd[i * 4 + r], -v);
        }
    }
}

// merged read scores + read-vector partials + last-block final output GEMV
__global__ void k_read(const float* __restrict__ Wro, float* __restrict__ out) {
    __shared__ float sS1[256], sS2[256];
    __shared__ float ssum[8][4];
    __shared__ int s_last;
    const int tid = threadIdx.x;
    sS1[tid] = 0.f; sS2[tid] = 0.f;
    __syncthreads();
    const int w = tid >> 5, lane = tid & 31;
    const int wg = blockIdx.x * 8 + w;
    const float k0a = g_krn[lane], k0b = g_krn[32 + lane];
    const float k1a = g_krn[64 + lane], k1b = g_krn[96 + lane];
    const float k2a = g_krn[128 + lane], k2b = g_krn[160 + lane];
    const float k3a = g_krn[192 + lane], k3b = g_krn[224 + lane];
    const float br0 = g_bread[0], br1 = g_bread[1], br2 = g_bread[2], br3 = g_bread[3];
    const float rb0 = g_rm[0], rb1 = g_rm[1], rb2 = g_rm[2], rb3 = g_rm[3];
    const float rf0 = g_rm[8], rf1 = g_rm[9], rf2 = g_rm[10], rf3 = g_rm[11];
    float p1[8] = {0, 0, 0, 0, 0, 0, 0, 0};
    float p2[8] = {0, 0, 0, 0, 0, 0, 0, 0};
    float l0 = 0.f, l1 = 0.f, l2 = 0.f, l3 = 0.f;
    for (int rr = 0; rr < 16; rr++) {
        int i = wg * 16 + rr;
        const float* row = g_M + (size_t)i * WD;
        float a0 = row[lane], a1 = row[lane + 32];
        float ss = a0 * a0 + a1 * a1;
        float d0 = a0 * k0a + a1 * k0b;
        float d1 = a0 * k1a + a1 * k1b;
        float d2 = a0 * k2a + a1 * k2b;
        float d3 = a0 * k3a + a1 * k3b;
        for (int o = 16; o; o >>= 1) {
            ss += __shfl_xor_sync(0xffffffffu, ss, o);
            d0 += __shfl_xor_sync(0xffffffffu, d0, o);
            d1 += __shfl_xor_sync(0xffffffffu, d1, o);
            d2 += __shfl_xor_sync(0xffffffffu, d2, o);
            d3 += __shfl_xor_sync(0xffffffffu, d3, o);
        }
        float inv = rsqrtf(fmaxf(ss, 1e-12f));
        float e0 = expf(br0 * d0 * inv), e1 = expf(br1 * d1 * inv);
        float e2 = expf(br2 * d2 * inv), e3 = expf(br3 * d3 * inv);
        float w20 = rb0 * g_Wbwd[i * 4 + 0] + rf0 * g_Wfwd[i * 4 + 0];
        float w21 = rb1 * g_Wbwd[i * 4 + 1] + rf1 * g_Wfwd[i * 4 + 1];
        float w22 = rb2 * g_Wbwd[i * 4 + 2] + rf2 * g_Wfwd[i * 4 + 2];
        float w23 = rb3 * g_Wbwd[i * 4 + 3] + rf3 * g_Wfwd[i * 4 + 3];
        p1[0] += a0 * e0; p1[1] += a1 * e0; p1[2] += a0 * e1; p1[3] += a1 * e1;
        p1[4] += a0 * e2; p1[5] += a1 * e2; p1[6] += a0 * e3; p1[7] += a1 * e3;
        p2[0] += a0 * w20; p2[1] += a1 * w20; p2[2] += a0 * w21; p2[3] += a1 * w21;
        p2[4] += a0 * w22; p2[5] += a1 * w22; p2[6] += a0 * w23; p2[7] += a1 * w23;
        if (lane == 0) { l0 += e0; l1 += e1; l2 += e2; l3 += e3; }
    }
#pragma unroll
    for (int r = 0; r < 4; r++) {
        atomicAdd(&sS1[r * 64 + lane], p1[r * 2]);
        atomicAdd(&sS1[r * 64 + 32 + lane], p1[r * 2 + 1]);
        atomicAdd(&sS2[r * 64 + lane], p2[r * 2]);
        atomicAdd(&sS2[r * 64 + 32 + lane], p2[r * 2 + 1]);
    }
    if (lane == 0) { ssum[w][0] = l0; ssum[w][1] = l1; ssum[w][2] = l2; ssum[w][3] = l3; }
    __syncthreads();
    atomicAdd(&g_S1[tid], sS1[tid]);
    atomicAdd(&g_S2[tid], sS2[tid]);
    if (tid < 4) {
        float s = 0.f;
        for (int k = 0; k < 8; k++) s += ssum[k][tid];
        atomicAdd(&g_sumr[tid], s);
    }
    __threadfence();
    __syncthreads();
    if (tid == 0) s_last = (atomicAdd(&g_rcnt, 1) == 63);
    __syncthreads();
    if (!s_last) return;
    if (tid == 0) g_rcnt = 0;
    __shared__ float s_rv[256];
    const int r = tid >> 6;
    s_rv[tid] = g_S2[tid] + g_rm[4 + r] * g_S1[tid] / g_sumr[r];
    __syncthreads();
    float acc = g_outv[tid];
#pragma unroll 8
    for (int k = 0; k < 256; k++) acc += s_rv[k] * Wro[k * 256 + tid];
    out[tid] = acc;
}

extern "C" void kernel_launch(void* const* d_in, const int* in_sizes, int n_in,
                              void* d_out, int out_size) {
    const float* x = (const float*)d_in[0];
    const float* dense_k = (const float*)d_in[1];
    const float* dense_b = (const float*)d_in[2];
    const float* lstm_k = (const float*)d_in[3];
    const float* lstm_r = (const float*)d_in[4];
    const float* lstm_b = (const float*)d_in[5];
    const float* W_output = (const float*)d_in[6];
    const float* W_interface = (const float*)d_in[7];
    const float* W_read_out = (const float*)d_in[8];
    const float* h = (const float*)d_in[9];
    const float* c = (const float*)d_in[10];
    const float* M = (const float*)d_in[11];
    const float* usage = (const float*)d_in[12];
    const float* L = (const float*)d_in[13];
    const float* W_prec = (const float*)d_in[14];
    const float* W_read = (const float*)d_in[15];
    const float* W_write = (const float*)d_in[16];
    const float* read_v = (const float*)d_in[17];
    float* out = (float*)d_out;

    k_init<<<8, 1024>>>(x, dense_k, dense_b, h, c, read_v);
    for (int t = 0; t < 5; t++) {
        k_lstmA<<<dim3(6, LKS), 128>>>(lstm_k, lstm_r, t);
        k_gate<<<1, 736>>>(lstm_b, t);
    }
    k_proj<<<dim3(3, KS2), 256>>>(W_output, W_interface);
    k_parse<<<1, 1024>>>();
    k_rankws<<<320, 256>>>(usage, W_read, W_write, M);
    k_alloc<<<1, 1024>>>();
    k_writeM<<<512, 256>>>(M);
    k_link<<<dim3(32, 16), 256>>>(L, W_prec, W_read);
    k_read<<<64, 256>>>(W_read_out, out);
}

// round 17
// speedup vs baseline: 1.0406x; 1.0406x over previous
#include <cuda_runtime.h>
#include <math.h>

#define NN 8192
#define WD 64
#define OUTD 256
#define IFACED 471
#define CD 727
#define FCD 2908
#define J4 727
#define LKS 64
#define KS2 32

typedef unsigned long long ull;

__device__ __align__(16) float g_seq[5 * WD];
__device__ float g_h[CD], g_c[CD];
__device__ __align__(16) float g_zb[5 * FCD];
__device__ float g_oppart[KS2 * CD];
__device__ float g_outv[OUTD];
__device__ float g_kwn[WD];
__device__ float g_krn[4 * WD];
__device__ float g_bread[4], g_bwrite;
__device__ __align__(16) float g_erase[WD];
__device__ __align__(16) float g_writev[WD];
__device__ float g_free[4], g_ag, g_wg;
__device__ float g_rm[12];
__device__ float g_usage[NN];
__device__ int   g_rank_[NN];
__device__ float g_Walloc[NN];
__device__ float g_ew[NN];
__device__ float g_sumw;
__device__ __align__(16) float g_Ww[NN];
__device__ __align__(16) float g_M[NN * WD];
__device__ __align__(16) float g_Wfwd[NN * 4];
__device__ __align__(16) float g_Wbwd[NN * 4];
__device__ float g_S1[256], g_S2[256], g_sumr[4];

__device__ __forceinline__ float sigm(float x) { return 1.f / (1.f + expf(-x)); }
__device__ __forceinline__ float sp(float x) { return x > 20.f ? x : log1pf(expf(x)); }
__device__ __forceinline__ void gdep_wait() { asm volatile("griddepcontrol.wait;" ::: "memory"); }

// ---- packed f32x2 helpers (sm_103a) ----
__device__ __forceinline__ ull pk2(float lo, float hi) {
    ull d; asm("mov.b64 %0, {%1,%2};" : "=l"(d) : "f"(lo), "f"(hi)); return d;
}
__device__ __forceinline__ float2 up2(ull v) {
    float2 r; asm("mov.b64 {%0,%1}, %2;" : "=f"(r.x), "=f"(r.y) : "l"(v)); return r;
}
__device__ __forceinline__ ull fma2_(ull a, ull b, ull c) {
    ull d; asm("fma.rn.f32x2 %0, %1, %2, %3;" : "=l"(d) : "l"(a), "l"(b), "l"(c)); return d;
}
__device__ __forceinline__ ull add2_(ull a, ull b) {
    ull d; asm("add.rn.f32x2 %0, %1, %2;" : "=l"(d) : "l"(a), "l"(b)); return d;
}
__device__ __forceinline__ ull mul2_(ull a, ull b) {
    ull d; asm("mul.rn.f32x2 %0, %1, %2;" : "=l"(d) : "l"(a), "l"(b)); return d;
}

// init: xd/seq, h/c copy, z-buffers preloaded with lstm bias
__global__ void k_init(const float* __restrict__ x, const float* __restrict__ dk,
                       const float* __restrict__ db, const float* __restrict__ h,
                       const float* __restrict__ c, const float* __restrict__ read_v,
                       const float* __restrict__ lstm_b) {
    int t = threadIdx.x;
    if (t < WD) {
        float acc = db[t];
#pragma unroll 8
        for (int k = 0; k < 256; k++) acc += x[k] * dk[k * WD + t];
        g_seq[t] = acc;
    }
    if (t < 256) g_seq[WD + t] = read_v[t];
    if (t < CD) { g_h[t] = h[t]; g_c[t] = c[t]; }
    for (int i = t; i < 5 * FCD; i += 1024) g_zb[i] = lstm_b[i % FCD];
}

// split-K LSTM matvec; weight loads hoisted BEFORE griddepcontrol.wait (prefetch)
__global__ void __launch_bounds__(128) k_lstmA(const float* __restrict__ lstm_k,
                                               const float* __restrict__ lstm_r, int t) {
    __shared__ float s_h[12];
    const int j4 = blockIdx.x * 128 + threadIdx.x;
    const int j4c = min(j4, J4 - 1);
    const int kc = blockIdx.y;
    const int k0 = kc * 12;
    const int kn = min(12, CD - k0);
    const float4* lr = (const float4*)lstm_r;
    float4 rv[12];
#pragma unroll
    for (int k = 0; k < 12; k++) {
        int row = min(k0 + k, CD - 1);
        rv[k] = lr[(size_t)row * J4 + j4c];
    }
    float4 kv = ((const float4*)lstm_k)[kc * J4 + j4c];
    gdep_wait();
    if (threadIdx.x < 12) s_h[threadIdx.x] = (threadIdx.x < kn) ? g_h[k0 + threadIdx.x] : 0.f;
    __syncthreads();
    if (j4 >= J4) return;
    float xs = g_seq[t * WD + kc];
    float ax = xs * kv.x, ay = xs * kv.y, az = xs * kv.z, aw = xs * kv.w;
#pragma unroll
    for (int k = 0; k < 12; k++) {
        float hv = s_h[k];
        ax += hv * rv[k].x; ay += hv * rv[k].y; az += hv * rv[k].z; aw += hv * rv[k].w;
    }
    float* zb = g_zb + t * FCD;
    atomicAdd(&zb[j4 * 4 + 0], ax);
    atomicAdd(&zb[j4 * 4 + 1], ay);
    atomicAdd(&zb[j4 * 4 + 2], az);
    atomicAdd(&zb[j4 * 4 + 3], aw);
}

__global__ void k_gate(int t) {
    gdep_wait();
    const int j = threadIdx.x;
    if (j >= CD) return;
    const float* zb = g_zb + t * FCD;
    float zi = zb[j], zf = zb[CD + j], zg = zb[2 * CD + j], zo = zb[3 * CD + j];
    float cn = sigm(zf) * g_c[j] + sigm(zi) * tanhf(zg);
    g_c[j] = cn;
    g_h[j] = sigm(zo) * tanhf(cn);
}

__global__ void k_proj(const float* __restrict__ Wout, const float* __restrict__ Wif) {
    __shared__ float sh[23];
    const int j = blockIdx.x * 256 + threadIdx.x;
    const int kc = blockIdx.y;
    const int k0 = kc * 23;
    const int kn = min(23, CD - k0);
    float wreg[23];
    if (j < CD) {
        if (j < 256) {
#pragma unroll
            for (int k = 0; k < 23; k++)
                wreg[k] = (k < kn) ? Wout[(size_t)(k0 + k) * 256 + j] : 0.f;
        } else {
            int jj = j - 256;
#pragma unroll
            for (int k = 0; k < 23; k++)
                wreg[k] = (k < kn) ? Wif[(size_t)(k0 + k) * IFACED + jj] : 0.f;
        }
    }
    gdep_wait();
    if (threadIdx.x < 23) sh[threadIdx.x] = (threadIdx.x < kn) ? g_h[k0 + threadIdx.x] : 0.f;
    __syncthreads();
    if (j >= CD) return;
    float acc = 0.f;
#pragma unroll
    for (int k = 0; k < 23; k++) acc += sh[k] * wreg[k];
    g_oppart[kc * CD + j] = acc;
}

__global__ void k_parse() {
    __shared__ float sif[IFACED];
    gdep_wait();
    const int t = threadIdx.x;
    if (t < CD) {
        float v = 0.f;
#pragma unroll
        for (int p = 0; p < KS2; p++) v += g_oppart[p * CD + t];
        if (t < 256) g_outv[t] = v; else sif[t - 256] = v;
    }
    __syncthreads();
    const int w = t >> 5, lane = t & 31;
    if (w == 0) {
        float s = 0.f;
        for (int e = lane; e < 64; e += 32) { float v = sif[260 + e]; s += v * v; }
        for (int o = 16; o; o >>= 1) s += __shfl_xor_sync(0xffffffffu, s, o);
        float inv = rsqrtf(fmaxf(s, 1e-12f));
        for (int e = lane; e < 64; e += 32) g_kwn[e] = sif[260 + e] * inv;
    } else if (w <= 4) {
        int r = w - 1;
        float s = 0.f;
        for (int e = lane; e < 64; e += 32) { float v = sif[r * 64 + e]; s += v * v; }
        for (int o = 16; o; o >>= 1) s += __shfl_xor_sync(0xffffffffu, s, o);
        float inv = rsqrtf(fmaxf(s, 1e-12f));
        for (int e = lane; e < 64; e += 32) g_krn[r * 64 + e] = sif[r * 64 + e] * inv;
    } else if (w == 5) {
        if (lane < 4) g_bread[lane] = 1.f + sp(sif[256 + lane]);
        if (lane == 4) g_bwrite = 1.f + sp(sif[324]);
        if (lane >= 8 && lane < 12) g_free[lane - 8] = sigm(sif[453 + lane - 8]);
        if (lane == 12) g_ag = sigm(sif[457]);
        if (lane == 13) g_wg = sigm(sif[458]);
        if (lane >= 16 && lane < 20) {
            int r = lane - 16;
            float e0 = expf(sif[459 + r]);
            float e1 = expf(sif[463 + r]);
            float e2 = expf(sif[467 + r]);
            float si = 1.f / (e0 + e1 + e2);
            g_rm[r] = e0 * si; g_rm[4 + r] = e1 * si; g_rm[8 + r] = e2 * si;
        }
    } else if (w == 6) {
        for (int e = lane; e < 64; e += 32) {
            g_erase[e] = sigm(sif[325 + e]);
            g_writev[e] = sif[389 + e];
        }
    }
}

__device__ __forceinline__ float usage_mk(float u, float4 wr, float ww,
                                          float f0, float f1, float f2, float f3) {
    float ret = 1.f;
    ret *= (1.f - f0 * wr.x);
    ret *= (1.f - f1 * wr.y);
    ret *= (1.f - f2 * wr.z);
    ret *= (1.f - f3 * wr.w);
    return (u + ww - u * ww) * ret;
}

// blocks 0..255: usage + brute-force stable rank + accumulator zeroing
// blocks 256..319: write content scores
__global__ void k_rankws(const float* __restrict__ usage_in, const float* __restrict__ Wread_in,
                         const float* __restrict__ Wwrite_in, const float* __restrict__ M) {
    __shared__ ull s_k[256];
    __shared__ float bsum[8];
    const int b = blockIdx.x, tid = threadIdx.x;
    if (b < 256) {
        const int bi = b >> 5, bj = b & 31;
        const float4* wr4 = (const float4*)Wread_in;
        const int jg = bj * 256 + tid;
        float ju = usage_in[jg]; float4 jwr = wr4[jg]; float jww = Wwrite_in[jg];
        const int i0 = bi * 1024 + tid * 4;
        float iu[4], iww[4]; float4 iwr[4];
#pragma unroll
        for (int m = 0; m < 4; m++) {
            iu[m] = usage_in[i0 + m]; iwr[m] = wr4[i0 + m]; iww[m] = Wwrite_in[i0 + m];
        }
        gdep_wait();
        const float f0 = g_free[0], f1 = g_free[1], f2 = g_free[2], f3 = g_free[3];
        {
            float uu = usage_mk(ju, jwr, jww, f0, f1, f2, f3);
            s_k[tid] = ((ull)__float_as_uint(uu) << 13) | (unsigned)jg;
        }
        __syncthreads();
        ull ki[4];
#pragma unroll
        for (int m = 0; m < 4; m++) {
            float uu = usage_mk(iu[m], iwr[m], iww[m], f0, f1, f2, f3);
            ki[m] = ((ull)__float_as_uint(uu) << 13) | (unsigned)(i0 + m);
            if (bj == 0) g_usage[i0 + m] = uu;
        }
        int c0 = 0, c1 = 0, c2 = 0, c3 = 0;
#pragma unroll 8
        for (int jj = 0; jj < 256; jj++) {
            ull kj = s_k[jj];
            c0 += (kj < ki[0]); c1 += (kj < ki[1]); c2 += (kj < ki[2]); c3 += (kj < ki[3]);
        }
        atomicAdd(&g_rank_[i0 + 0], c0);
        atomicAdd(&g_rank_[i0 + 1], c1);
        atomicAdd(&g_rank_[i0 + 2], c2);
        atomicAdd(&g_rank_[i0 + 3], c3);
        if (bi == 0) {
            float4 z4 = make_float4(0.f, 0.f, 0.f, 0.f);
            ((float4*)g_Wfwd)[bj * 256 + tid] = z4;
            ((float4*)g_Wbwd)[bj * 256 + tid] = z4;
            if (bj == 0) {
                g_S1[tid] = 0.f; g_S2[tid] = 0.f;
                if (tid < 4) g_sumr[tid] = 0.f;
                if (tid == 0) g_sumw = 0.f;
            }
        }
    } else {
        gdep_wait();
        const int w = tid >> 5, lane = tid & 31;
        const int wg = (b - 256) * 8 + w;
        const float ka = g_kwn[lane], kb = g_kwn[lane + 32];
        const float bw = g_bwrite;
        float local = 0.f;
        for (int rr = 0; rr < 16; rr++) {
            int i = wg * 16 + rr;
            const float* row = M + (size_t)i * WD;
            float a0 = row[lane], a1 = row[lane + 32];
            float ss = a0 * a0 + a1 * a1;
            float d = a0 * ka + a1 * kb;
            for (int o = 16; o; o >>= 1) {
                ss += __shfl_xor_sync(0xffffffffu, ss, o);
                d += __shfl_xor_sync(0xffffffffu, d, o);
            }
            if (lane == 0) {
                float e = expf(bw * d * rsqrtf(fmaxf(ss, 1e-12f)));
                g_ew[i] = e;
                local += e;
            }
        }
        if (lane == 0) bsum[w] = local;
        __syncthreads();
        if (tid == 0) {
            float s = 0.f;
            for (int k = 0; k < 8; k++) s += bsum[k];
            atomicAdd(&g_sumw, s);
        }
    }
}

__global__ void k_alloc() {
    __shared__ float s_s[NN];
    __shared__ float wtot[32];
    gdep_wait();
    const int t = threadIdx.x;
    for (int i = t; i < NN; i += 1024) s_s[g_rank_[i]] = g_usage[i];
    __syncthreads();
    float loc[8], p = 1.f;
#pragma unroll
    for (int m = 0; m < 8; m++) { loc[m] = p; p *= s_s[t * 8 + m]; }
    const int lane = t & 31, w = t >> 5;
    float sc = p;
    for (int o = 1; o < 32; o <<= 1) {
        float v = __shfl_up_sync(0xffffffffu, sc, o);
        if (lane >= o) sc *= v;
    }
    if (lane == 31) wtot[w] = sc;
    __syncthreads();
    if (w == 0) {
        float s2 = wtot[lane];
        for (int o = 1; o < 32; o <<= 1) {
            float z = __shfl_up_sync(0xffffffffu, s2, o);
            if (lane >= o) s2 *= z;
        }
        wtot[lane] = s2;
    }
    __syncthreads();
    float excl = __shfl_up_sync(0xffffffffu, sc, 1);
    if (lane == 0) excl = 1.f;
    float pref = (w > 0 ? wtot[w - 1] : 1.f) * excl;
#pragma unroll
    for (int m = 0; m < 8; m++) s_s[t * 8 + m] = pref * loc[m];
    __syncthreads();
    for (int i = t; i < NN; i += 1024) {
        float u = g_usage[i];
        g_Walloc[i] = (1.f - u) * s_s[g_rank_[i]];
        g_rank_[i] = 0;
    }
}

__global__ void k_writeM(const float* __restrict__ M) {
    const int e4 = blockIdx.x * 256 + threadIdx.x;
    const int i = e4 >> 4, wc = (e4 & 15) << 2;
    float4 m = ((const float4*)M)[e4];
    gdep_wait();
    const float inv_s = 1.f / g_sumw;
    const float wgt = g_wg, ag = g_ag, iag = 1.f - g_ag;
    float ww = wgt * (ag * g_Walloc[i] + iag * g_ew[i] * inv_s);
    float4 er = *(const float4*)(g_erase + wc);
    float4 wv = *(const float4*)(g_writev + wc);
    float4 o;
    o.x = m.x * (1.f - ww * er.x) + ww * wv.x;
    o.y = m.y * (1.f - ww * er.y) + ww * wv.y;
    o.z = m.z * (1.f - ww * er.z) + ww * wv.z;
    o.w = m.w * (1.f - ww * er.w) + ww * wv.w;
    ((float4*)g_M)[e4] = o;
    if ((e4 & 15) == 0) g_Ww[i] = ww;
}

// fused: W_fwd = L_new @ Wr, W_bwd = L_new^T @ Wr; L_new on the fly; f32x2 packed;
// diagonal via epilogue subtraction; input loads hoisted pre-wait
__global__ void __launch_bounds__(256) k_link(const float* __restrict__ L,
                                              const float* __restrict__ Wprec,
                                              const float* __restrict__ Wread) {
    __shared__ float s_ww[512];
    __shared__ float s_wr[512 * 4];
    __shared__ float s_red[8][1024];
    const int jb = blockIdx.x, ib = blockIdx.y;
    const int i0 = ib * 512;
    for (int k = threadIdx.x; k < 512; k += 256) {
        float4 v = ((const float4*)Wread)[i0 + k];
        s_wr[k * 4] = v.x; s_wr[k * 4 + 1] = v.y; s_wr[k * 4 + 2] = v.z; s_wr[k * 4 + 3] = v.w;
    }
    const int w = threadIdx.x >> 5, lane = threadIdx.x & 31;
    const int j0 = jb * 256 + lane * 4;

    ull wpj2[4], wrj2[4][4], bwd2[4][4];
#pragma unroll
    for (int cc = 0; cc < 2; cc++)
#pragma unroll
        for (int p = 0; p < 2; p++) {
            int q = cc * 2 + p;
            int jj = j0 + cc * 128 + p * 2;
            wpj2[q] = pk2(Wprec[jj], Wprec[jj + 1]);
#pragma unroll
            for (int r = 0; r < 4; r++) {
                wrj2[q][r] = pk2(Wread[jj * 4 + r], Wread[(jj + 1) * 4 + r]);
                bwd2[q][r] = 0ull;
            }
        }
    const int c4 = j0 >> 2;
    float4 a0, a1, b0, b1;
    {
        const float4* LrA = (const float4*)(L + (size_t)(i0 + w) * NN);
        const float4* LrB = (const float4*)(L + (size_t)(i0 + w + 8) * NN);
        a0 = __ldcs(LrA + c4); a1 = __ldcs(LrA + c4 + 32);
        b0 = __ldcs(LrB + c4); b1 = __ldcs(LrB + c4 + 32);
    }
    gdep_wait();
    ull tj2[4];
#pragma unroll
    for (int cc = 0; cc < 2; cc++)
#pragma unroll
        for (int p = 0; p < 2; p++) {
            int jj = j0 + cc * 128 + p * 2;
            tj2[cc * 2 + p] = pk2(1.f - g_Ww[jj], 1.f - g_Ww[jj + 1]);
        }
    for (int k = threadIdx.x; k < 512; k += 256) s_ww[k] = g_Ww[i0 + k];
    __syncthreads();

    for (int it = 0; it < 32; it++) {
        const int il = w + it * 16;
        const int ia = i0 + il, ib2 = ia + 8;
        float4 ca0 = a0, ca1 = a1, cb0 = b0, cb1 = b1;
        if (it < 31) {
            const int iln = il + 16;
            const float4* LrA = (const float4*)(L + (size_t)(i0 + iln) * NN);
            const float4* LrB = (const float4*)(L + (size_t)(i0 + iln + 8) * NN);
            a0 = __ldcs(LrA + c4); a1 = __ldcs(LrA + c4 + 32);
            b0 = __ldcs(LrB + c4); b1 = __ldcs(LrB + c4 + 32);
        }
        float fa[4], fb[4];
        {
            float ww = s_ww[il];
            ull ww2 = pk2(ww, ww), wwn2 = pk2(-ww, -ww);
            ull le[4] = {pk2(ca0.x, ca0.y), pk2(ca0.z, ca0.w), pk2(ca1.x, ca1.y), pk2(ca1.z, ca1.w)};
            ull f2[4] = {0ull, 0ull, 0ull, 0ull};
            ull wri2[4];
#pragma unroll
            for (int r = 0; r < 4; r++) { float s = s_wr[il * 4 + r]; wri2[r] = pk2(s, s); }
#pragma unroll
            for (int q = 0; q < 4; q++) {
                ull nl2 = fma2_(add2_(tj2[q], wwn2), le[q], mul2_(ww2, wpj2[q]));
#pragma unroll
                for (int r = 0; r < 4; r++) {
                    f2[r] = fma2_(nl2, wrj2[q][r], f2[r]);
                    bwd2[q][r] = fma2_(nl2, wri2[r], bwd2[q][r]);
                }
            }
#pragma unroll
            for (int r = 0; r < 4; r++) { float2 t = up2(f2[r]); fa[r] = t.x + t.y; }
        }
        {
            float ww = s_ww[il + 8];
            ull ww2 = pk2(ww, ww), wwn2 = pk2(-ww, -ww);
            ull le[4] = {pk2(cb0.x, cb0.y), pk2(cb0.z, cb0.w), pk2(cb1.x, cb1.y), pk2(cb1.z, cb1.w)};
            ull f2[4] = {0ull, 0ull, 0ull, 0ull};
            ull wri2[4];
#pragma unroll
            for (int r = 0; r < 4; r++) { float s = s_wr[(il + 8) * 4 + r]; wri2[r] = pk2(s, s); }
#pragma unroll
            for (int q = 0; q < 4; q++) {
                ull nl2 = fma2_(add2_(tj2[q], wwn2), le[q], mul2_(ww2, wpj2[q]));
#pragma unroll
                for (int r = 0; r < 4; r++) {
                    f2[r] = fma2_(nl2, wrj2[q][r], f2[r]);
                    bwd2[q][r] = fma2_(nl2, wri2[r], bwd2[q][r]);
                }
            }
#pragma unroll
            for (int r = 0; r < 4; r++) { float2 t = up2(f2[r]); fb[r] = t.x + t.y; }
        }
#pragma unroll
        for (int o = 16; o; o >>= 1) {
#pragma unroll
            for (int r = 0; r < 4; r++) {
                fa[r] += __shfl_xor_sync(0xffffffffu, fa[r], o);
                fb[r] += __shfl_xor_sync(0xffffffffu, fb[r], o);
            }
        }
        if (lane < 4) {
            float fv = lane == 0 ? fa[0] : lane == 1 ? fa[1] : lane == 2 ? fa[2] : fa[3];
            atomicAdd(&g_Wfwd[ia * 4 + lane], fv);
            float gv = lane == 0 ? fb[0] : lane == 1 ? fb[1] : lane == 2 ? fb[2] : fb[3];
            atomicAdd(&g_Wfwd[ib2 * 4 + lane], gv);
        }
    }
#pragma unroll
    for (int cc = 0; cc < 2; cc++)
#pragma unroll
        for (int p = 0; p < 2; p++) {
            int q = cc * 2 + p;
            int col = cc * 128 + lane * 4 + p * 2;
#pragma unroll
            for (int r = 0; r < 4; r++) {
                float2 t = up2(bwd2[q][r]);
                s_red[w][col * 4 + r] = t.x;
                s_red[w][(col + 1) * 4 + r] = t.y;
            }
        }
    __syncthreads();
#pragma unroll
    for (int qq = 0; qq < 4; qq++) {
        int pos = qq * 256 + threadIdx.x;
        float v = 0.f;
#pragma unroll
        for (int ww2 = 0; ww2 < 8; ww2++) v += s_red[ww2][pos];
        atomicAdd(&g_Wbwd[jb * 1024 + pos], v);
    }
    if (ib == (jb >> 1)) {
        const int i = jb * 256 + threadIdx.x;
        const int il = i - i0;
        float wwi = s_ww[il];
        float nl = (1.f - 2.f * wwi) * __ldg(L + (size_t)i * NN + i) + wwi * __ldg(Wprec + i);
#pragma unroll
        for (int r = 0; r < 4; r++) {
            float v = nl * s_wr[il * 4 + r];
            atomicAdd(&g_Wfwd[i * 4 + r], -v);
            atomicAdd(&g_Wbwd[i * 4 + r], -v);
        }
    }
}

__global__ void k_read() {
    __shared__ float sS1[256], sS2[256];
    __shared__ float ssum[8][4];
    gdep_wait();
    const int tid = threadIdx.x;
    sS1[tid] = 0.f; sS2[tid] = 0.f;
    __syncthreads();
    const int w = tid >> 5, lane = tid & 31;
    const int wg = blockIdx.x * 8 + w;
    const float k0a = g_krn[lane], k0b = g_krn[32 + lane];
    const float k1a = g_krn[64 + lane], k1b = g_krn[96 + lane];
    const float k2a = g_krn[128 + lane], k2b = g_krn[160 + lane];
    const float k3a = g_krn[192 + lane], k3b = g_krn[224 + lane];
    const float br0 = g_bread[0], br1 = g_bread[1], br2 = g_bread[2], br3 = g_bread[3];
    const float rb0 = g_rm[0], rb1 = g_rm[1], rb2 = g_rm[2], rb3 = g_rm[3];
    const float rf0 = g_rm[8], rf1 = g_rm[9], rf2 = g_rm[10], rf3 = g_rm[11];
    float p1[8] = {0, 0, 0, 0, 0, 0, 0, 0};
    float p2[8] = {0, 0, 0, 0, 0, 0, 0, 0};
    float l0 = 0.f, l1 = 0.f, l2 = 0.f, l3 = 0.f;
    for (int rr = 0; rr < 16; rr++) {
        int i = wg * 16 + rr;
        const float* row = g_M + (size_t)i * WD;
        float a0 = row[lane], a1 = row[lane + 32];
        float ss = a0 * a0 + a1 * a1;
        float d0 = a0 * k0a + a1 * k0b;
        float d1 = a0 * k1a + a1 * k1b;
        float d2 = a0 * k2a + a1 * k2b;
        float d3 = a0 * k3a + a1 * k3b;
        for (int o = 16; o; o >>= 1) {
            ss += __shfl_xor_sync(0xffffffffu, ss, o);
            d0 += __shfl_xor_sync(0xffffffffu, d0, o);
            d1 += __shfl_xor_sync(0xffffffffu, d1, o);
            d2 += __shfl_xor_sync(0xffffffffu, d2, o);
            d3 += __shfl_xor_sync(0xffffffffu, d3, o);
        }
        float inv = rsqrtf(fmaxf(ss, 1e-12f));
        float e0 = expf(br0 * d0 * inv), e1 = expf(br1 * d1 * inv);
        float e2 = expf(br2 * d2 * inv), e3 = expf(br3 * d3 * inv);
        float w20 = rb0 * g_Wbwd[i * 4 + 0] + rf0 * g_Wfwd[i * 4 + 0];
        float w21 = rb1 * g_Wbwd[i * 4 + 1] + rf1 * g_Wfwd[i * 4 + 1];
        float w22 = rb2 * g_Wbwd[i * 4 + 2] + rf2 * g_Wfwd[i * 4 + 2];
        float w23 = rb3 * g_Wbwd[i * 4 + 3] + rf3 * g_Wfwd[i * 4 + 3];
        p1[0] += a0 * e0; p1[1] += a1 * e0; p1[2] += a0 * e1; p1[3] += a1 * e1;
        p1[4] += a0 * e2; p1[5] += a1 * e2; p1[6] += a0 * e3; p1[7] += a1 * e3;
        p2[0] += a0 * w20; p2[1] += a1 * w20; p2[2] += a0 * w21; p2[3] += a1 * w21;
        p2[4] += a0 * w22; p2[5] += a1 * w22; p2[6] += a0 * w23; p2[7] += a1 * w23;
        if (lane == 0) { l0 += e0; l1 += e1; l2 += e2; l3 += e3; }
    }
#pragma unroll
    for (int r = 0; r < 4; r++) {
        atomicAdd(&sS1[r * 64 + lane], p1[r * 2]);
        atomicAdd(&sS1[r * 64 + 32 + lane], p1[r * 2 + 1]);
        atomicAdd(&sS2[r * 64 + lane], p2[r * 2]);
        atomicAdd(&sS2[r * 64 + 32 + lane], p2[r * 2 + 1]);
    }
    if (lane == 0) { ssum[w][0] = l0; ssum[w][1] = l1; ssum[w][2] = l2; ssum[w][3] = l3; }
    __syncthreads();
    atomicAdd(&g_S1[tid], sS1[tid]);
    atomicAdd(&g_S2[tid], sS2[tid]);
    if (tid < 4) {
        float s = 0.f;
        for (int k = 0; k < 8; k++) s += ssum[k][tid];
        atomicAdd(&g_sumr[tid], s);
    }
}

__global__ void k_final(const float* __restrict__ Wro, float* __restrict__ out) {
    __shared__ float s_rv[256];
    gdep_wait();
    const int j = threadIdx.x;
    const int r = j >> 6;
    s_rv[j] = g_S2[j] + g_rm[4 + r] * g_S1[j] / g_sumr[r];
    __syncthreads();
    float acc = g_outv[j];
#pragma unroll 8
    for (int k = 0; k < 256; k++) acc += s_rv[k] * Wro[k * 256 + j];
    out[j] = acc;
}

template <typename... A>
static inline void pdl(dim3 g, dim3 b, void (*ker)(A...), A... args) {
    cudaLaunchConfig_t cfg = {};
    cfg.gridDim = g; cfg.blockDim = b; cfg.dynamicSmemBytes = 0; cfg.stream = 0;
    cudaLaunchAttribute at[1];
    at[0].id = cudaLaunchAttributeProgrammaticStreamSerialization;
    at[0].val.programmaticStreamSerializationAllowed = 1;
    cfg.attrs = at; cfg.numAttrs = 1;
    cudaLaunchKernelEx(&cfg, ker, args...);
}

extern "C" void kernel_launch(void* const* d_in, const int* in_sizes, int n_in,
                              void* d_out, int out_size) {
    const float* x = (const float*)d_in[0];
    const float* dense_k = (const float*)d_in[1];
    const float* dense_b = (const float*)d_in[2];
    const float* lstm_k = (const float*)d_in[3];
    const float* lstm_r = (const float*)d_in[4];
    const float* lstm_b = (const float*)d_in[5];
    const float* W_output = (const float*)d_in[6];
    const float* W_interface = (const float*)d_in[7];
    const float* W_read_out = (const float*)d_in[8];
    const float* h = (const float*)d_in[9];
    const float* c = (const float*)d_in[10];
    const float* M = (const float*)d_in[11];
    const float* usage = (const float*)d_in[12];
    const float* L = (const float*)d_in[13];
    const float* W_prec = (const float*)d_in[14];
    const float* W_read = (const float*)d_in[15];
    const float* W_write = (const float*)d_in[16];
    const float* read_v = (const float*)d_in[17];
    float* out = (float*)d_out;

    k_init<<<1, 1024>>>(x, dense_k, dense_b, h, c, read_v, lstm_b);
    for (int t = 0; t < 5; t++) {
        pdl(dim3(6, LKS), dim3(128), k_lstmA, lstm_k, lstm_r, t);
        pdl(dim3(1), dim3(736), k_gate, t);
    }
    pdl(dim3(3, KS2), dim3(256), k_proj, W_output, W_interface);
    pdl(dim3(1), dim3(1024), k_parse);
    pdl(dim3(320), dim3(256), k_rankws, usage, W_read, W_write, M);
    pdl(dim3(1), dim3(1024), k_alloc);
    pdl(dim3(512), dim3(256), k_writeM, M);
    pdl(dim3(32, 16), dim3(256), k_link, L, W_prec, W_read);
    pdl(dim3(64), dim3(256), k_read);
    pdl(dim3(1), dim3(256), k_final, W_read_out, out);
}